// round 9
// baseline (speedup 1.0000x reference)
#include <cuda_runtime.h>
#include <stdint.h>

// ---------------------------------------------------------------------------
// CAGAT_MinSum_Layer_Lite — cluster/DSMEM formulation.
//
// Measured wall (R4/R8): ~3 random L1tex wavefronts per edge (2 gathers +
// 1 atomic) at ~1 wf/cyc/SM  =>  ~343us structural floor for plain
// edge-parallel. This version caches 91.7% of the 4MB node table in the
// combined shared memory of a 16-CTA cluster (16 x 224KB = 3.58MB) and
// serves gathers via mapa + ld.shared::cluster (DSMEM), removing them from
// the global L1tex/L2 path. Atomics (1 wf/edge) remain the wall: ~155us.
// ---------------------------------------------------------------------------

#define CLUSTER_SZ    16
#define NCLUSTERS     8                         // 8 clusters x 16 CTAs = 128 SMs, 1 wave
#define TPB           1024
#define NODES_PER_CTA 57344                     // 57344 * 4B = 224KB smem per CTA
#define COVERED       (CLUSTER_SZ * NODES_PER_CTA)  // 917504 of 1M nodes (91.7%)
#define SMEM_BYTES    (NODES_PER_CTA * 4)       // 229376 <= 232448 max

__global__ void zero_out_kernel(float4* __restrict__ out, int n4) {
    int i = blockIdx.x * blockDim.x + threadIdx.x;
    if (i < n4) out[i] = make_float4(0.f, 0.f, 0.f, 0.f);
}

// Gather node_features[idx]: DSMEM if covered, else global (L2-resident tail).
__device__ __forceinline__ float gather_node(int idx, uint32_t smem_base,
                                             const float* __restrict__ nf) {
    if (idx < COVERED) {
        // owner = idx / 57344 = (idx >> 13) / 7 ; exact for idx < COVERED.
        uint32_t t     = ((uint32_t)idx) >> 13;
        uint32_t owner = (t * 9363u) >> 16;
        uint32_t local = (uint32_t)idx - owner * (uint32_t)NODES_PER_CTA;
        uint32_t laddr = smem_base + local * 4u;
        uint32_t raddr;
        asm("mapa.shared::cluster.u32 %0, %1, %2;" : "=r"(raddr) : "r"(laddr), "r"(owner));
        uint32_t v;
        asm volatile("ld.shared::cluster.b32 %0, [%1];" : "=r"(v) : "r"(raddr));
        return __uint_as_float(v);
    }
    return __ldg(nf + idx);
}

__global__ void __launch_bounds__(TPB, 1) cagat_cluster_kernel(
    const float* __restrict__ node_features,
    const int*   __restrict__ edge_src,
    const int*   __restrict__ edge_dst,
    const float* __restrict__ cycle_mask,
    const float* __restrict__ W,
    const float* __restrict__ b,
    const float* __restrict__ min_sum_scaler,
    const float* __restrict__ cycle_penalty,
    float* __restrict__ out,
    int num_edges)
{
    extern __shared__ float cache[];

    uint32_t rank;
    asm("mov.u32 %0, %%cluster_ctarank;" : "=r"(rank));

    // ---- Fill this CTA's 224KB slice: nodes [rank*57344, (rank+1)*57344) ----
    {
        const float4* src = reinterpret_cast<const float4*>(
            node_features + (size_t)rank * NODES_PER_CTA);
        float4* dst = reinterpret_cast<float4*>(cache);
        #pragma unroll
        for (int i = threadIdx.x; i < NODES_PER_CTA / 4; i += TPB)
            dst[i] = __ldg(src + i);
    }
    // Release our smem writes to the cluster; acquire peers' fills.
    asm volatile("barrier.cluster.arrive.aligned;" ::: "memory");
    asm volatile("barrier.cluster.wait.aligned;"   ::: "memory");

    uint32_t smem_base;
    asm("{ .reg .u64 t; cvta.to.shared.u64 t, %1; cvt.u32.u64 %0, t; }"
        : "=r"(smem_base) : "l"(cache));

    const float w0 = W[0], w1 = W[1], w2 = W[2];
    const float bb = b[0];
    const float ms = min_sum_scaler[0];
    const float cp = cycle_penalty[0];

    const int T   = gridDim.x * blockDim.x;                  // 131072
    const int tid = blockIdx.x * blockDim.x + threadIdx.x;

    // Grid-stride over edges, 4 per thread per iteration (int4/float4 streaming).
    for (int base = tid * 4; base < num_edges; base += T * 4) {
        const int4   s4  = *reinterpret_cast<const int4*>(edge_src + base);
        const int4   d4  = *reinterpret_cast<const int4*>(edge_dst + base);
        const float4 cm4 = *reinterpret_cast<const float4*>(cycle_mask + base);

        const int   srcs[4] = { s4.x, s4.y, s4.z, s4.w };
        const int   dsts[4] = { d4.x, d4.y, d4.z, d4.w };
        const float cms[4]  = { cm4.x, cm4.y, cm4.z, cm4.w };

        float xs[4], xd[4];
        #pragma unroll
        for (int k = 0; k < 4; ++k) {
            xs[k] = gather_node(srcs[k], smem_base, node_features);
            xd[k] = gather_node(dsts[k], smem_base, node_features);
        }

        #pragma unroll
        for (int k = 0; k < 4; ++k) {
            const float cm = cms[k];
            float raw = fmaf(xs[k], w0, fmaf(xd[k], w1, fmaf(cm, w2, bb)));
            raw = (raw > 0.f) ? raw : 0.01f * raw;            // leaky_relu
            raw = fmaf(cm, cp, raw);
            const float att = __frcp_rn(1.f + __expf(-raw));  // sigmoid
            atomicAdd(out + dsts[k], xs[k] * att * ms);       // REDG
        }
    }

    // No CTA may exit while peers might still read its smem.
    asm volatile("barrier.cluster.arrive.aligned;" ::: "memory");
    asm volatile("barrier.cluster.wait.aligned;"   ::: "memory");
}

extern "C" void kernel_launch(void* const* d_in, const int* in_sizes, int n_in,
                              void* d_out, int out_size) {
    const float* node_features  = (const float*)d_in[0];
    const int*   edge_index     = (const int*)d_in[1];   // [2, E] int32
    const float* cycle_mask     = (const float*)d_in[2];
    const float* W              = (const float*)d_in[3];
    const float* b              = (const float*)d_in[4];
    const float* min_sum_scaler = (const float*)d_in[5];
    const float* cycle_penalty  = (const float*)d_in[6];
    float*       out            = (float*)d_out;

    const int num_edges = in_sizes[2];
    const int num_nodes = out_size;

    // 1) Zero the (poisoned) output.
    {
        int n4 = num_nodes / 4;
        zero_out_kernel<<<(n4 + 255) / 256, 256>>>((float4*)out, n4);
    }

    // 2) Cluster kernel: opt-in attributes (idempotent each call).
    cudaFuncSetAttribute(cagat_cluster_kernel,
                         cudaFuncAttributeMaxDynamicSharedMemorySize, SMEM_BYTES);
    cudaFuncSetAttribute(cagat_cluster_kernel,
                         cudaFuncAttributeNonPortableClusterSizeAllowed, 1);

    cudaLaunchConfig_t cfg = {};
    cfg.gridDim  = dim3(NCLUSTERS * CLUSTER_SZ, 1, 1);   // 128 CTAs
    cfg.blockDim = dim3(TPB, 1, 1);
    cfg.dynamicSmemBytes = SMEM_BYTES;
    cfg.stream = 0;

    cudaLaunchAttribute attr[1];
    attr[0].id = cudaLaunchAttributeClusterDimension;
    attr[0].val.clusterDim.x = CLUSTER_SZ;
    attr[0].val.clusterDim.y = 1;
    attr[0].val.clusterDim.z = 1;
    cfg.attrs = attr;
    cfg.numAttrs = 1;

    const int* edge_src = edge_index;
    const int* edge_dst = edge_index + num_edges;

    cudaLaunchKernelEx(&cfg, cagat_cluster_kernel,
                       node_features, edge_src, edge_dst, cycle_mask,
                       W, b, min_sum_scaler, cycle_penalty, out, num_edges);
}

// round 11
// speedup vs baseline: 4.4240x; 4.4240x over previous
#include <cuda_runtime.h>
#include <stdint.h>

// ---------------------------------------------------------------------------
// CAGAT_MinSum_Layer_Lite: edge-parallel gather/compute/scatter-add.
//   raw  = x_src*W0 + x_dst*W1 + cm*W2 + b
//   raw  = leaky_relu(raw, 0.01) + cm * cycle_penalty
//   att  = sigmoid(raw)
//   out[dst] += x_src * att * min_sum_scaler     (segment_sum via REDG)
//
// Measured floor: ~3 random LSU ops/edge (2 gather wavefronts + 1 RED lane)
// ≈ 324us serialized per-SM, L2 at ~85% LTS cap. R9 showed DSMEM gathers are
// 4.5x WORSE (random 4B DSMEM loads serialize at owner crossbar). This is the
// best-known R4 shape (4 edges/thread, 32 regs, occ ~92%) + evict_last L1
// hint on node gathers so the node table outcompetes the 400MB edge stream
// for L1 residency.
// ---------------------------------------------------------------------------

__global__ void zero_out_kernel(float4* __restrict__ out, int n4) {
    int i = blockIdx.x * blockDim.x + threadIdx.x;
    if (i < n4) out[i] = make_float4(0.f, 0.f, 0.f, 0.f);
}

// Read-only gather with L1 evict_last priority (node table wants residency).
__device__ __forceinline__ float ldg_node(const float* __restrict__ p) {
    float v;
    asm volatile("ld.global.nc.L1::evict_last.f32 %0, [%1];" : "=f"(v) : "l"(p));
    return v;
}

__global__ __launch_bounds__(256, 8) void cagat_edge_kernel(
    const float* __restrict__ node_features,
    const int*   __restrict__ edge_src,       // edge_index[0, :]
    const int*   __restrict__ edge_dst,       // edge_index[1, :]
    const float* __restrict__ cycle_mask,
    const float* __restrict__ W,              // [3]
    const float* __restrict__ b,              // [1]
    const float* __restrict__ min_sum_scaler, // [1]
    const float* __restrict__ cycle_penalty,  // [1]
    float* __restrict__ out,
    int num_edges)                            // divisible by 4 (33554432)
{
    const int t  = blockIdx.x * blockDim.x + threadIdx.x;
    const int e0 = t * 4;
    if (e0 >= num_edges) return;

    const float w0 = W[0], w1 = W[1], w2 = W[2];
    const float bb = b[0];
    const float ms = min_sum_scaler[0];
    const float cp = cycle_penalty[0];

    // Streaming loads (default policy — __ldcs measured +1.2% in R8).
    const int4   s4  = *reinterpret_cast<const int4*>(edge_src + e0);
    const int4   d4  = *reinterpret_cast<const int4*>(edge_dst + e0);
    const float4 cm4 = *reinterpret_cast<const float4*>(cycle_mask + e0);

    const int   srcs[4] = { s4.x, s4.y, s4.z, s4.w };
    const int   dsts[4] = { d4.x, d4.y, d4.z, d4.w };
    const float cms[4]  = { cm4.x, cm4.y, cm4.z, cm4.w };

    // Batch the 8 scattered gathers first: overlap L1/L2 latencies.
    float xs[4], xd[4];
    #pragma unroll
    for (int k = 0; k < 4; ++k) {
        xs[k] = ldg_node(node_features + srcs[k]);
        xd[k] = ldg_node(node_features + dsts[k]);
    }

    #pragma unroll
    for (int k = 0; k < 4; ++k) {
        const float cm = cms[k];
        float raw = fmaf(xs[k], w0, fmaf(xd[k], w1, fmaf(cm, w2, bb)));
        raw = (raw > 0.f) ? raw : 0.01f * raw;            // leaky_relu
        raw = fmaf(cm, cp, raw);
        const float att = __frcp_rn(1.f + __expf(-raw));  // sigmoid
        const float msg = xs[k] * att * ms;
        atomicAdd(out + dsts[k], msg);                    // REDG (return unused)
    }
}

extern "C" void kernel_launch(void* const* d_in, const int* in_sizes, int n_in,
                              void* d_out, int out_size) {
    const float* node_features  = (const float*)d_in[0];
    const int*   edge_index     = (const int*)d_in[1];   // [2, E] int32
    const float* cycle_mask     = (const float*)d_in[2];
    const float* W              = (const float*)d_in[3];
    const float* b              = (const float*)d_in[4];
    const float* min_sum_scaler = (const float*)d_in[5];
    const float* cycle_penalty  = (const float*)d_in[6];
    float*       out            = (float*)d_out;

    const int num_edges = in_sizes[2];          // cycle_mask length = E
    const int num_nodes = out_size;

    // 1) Zero the (poisoned) output.
    {
        int n4 = num_nodes / 4;
        int threads = 256;
        int blocks = (n4 + threads - 1) / threads;
        zero_out_kernel<<<blocks, threads>>>((float4*)out, n4);
    }

    // 2) Edge kernel: 4 edges/thread.
    {
        int threads = 256;
        int nthreads = num_edges / 4;
        int blocks = (nthreads + threads - 1) / threads;
        cagat_edge_kernel<<<blocks, threads>>>(
            node_features,
            edge_index,                // row 0: src
            edge_index + num_edges,    // row 1: dst
            cycle_mask,
            W, b, min_sum_scaler, cycle_penalty,
            out, num_edges);
    }
}

// round 14
// speedup vs baseline: 4.4503x; 1.0059x over previous
#include <cuda_runtime.h>
#include <stdint.h>

// ---------------------------------------------------------------------------
// CAGAT_MinSum_Layer_Lite: edge-parallel gather/compute/scatter-add.
//   raw  = x_src*W0 + x_dst*W1 + cm*W2 + b
//   raw  = leaky_relu(raw, 0.01) + cm * cycle_penalty
//   att  = sigmoid(raw)
//   out[dst] += x_src * att * min_sum_scaler     (segment_sum via REDG)
//
// Final formulation: measured at the random-access wavefront roofline
// (~3 L1tex/LSU wavefronts per edge; L2 at ~81% of LTS sector cap).
// Cache-policy variants (__ldcs, evict_last) measured neutral-to-worse vs
// plain __ldg; 8 edges/thread regressed via occupancy loss; DSMEM cluster
// caching regressed 4.5x. This is the best-measured R4 body; block=512 is
// the last free tie-break knob.
// ---------------------------------------------------------------------------

__global__ void zero_out_kernel(float4* __restrict__ out, int n4) {
    int i = blockIdx.x * blockDim.x + threadIdx.x;
    if (i < n4) out[i] = make_float4(0.f, 0.f, 0.f, 0.f);
}

__global__ __launch_bounds__(512, 4) void cagat_edge_kernel(
    const float* __restrict__ node_features,
    const int*   __restrict__ edge_src,       // edge_index[0, :]
    const int*   __restrict__ edge_dst,       // edge_index[1, :]
    const float* __restrict__ cycle_mask,
    const float* __restrict__ W,              // [3]
    const float* __restrict__ b,              // [1]
    const float* __restrict__ min_sum_scaler, // [1]
    const float* __restrict__ cycle_penalty,  // [1]
    float* __restrict__ out,
    int num_edges)                            // divisible by 4 (33554432)
{
    const int t  = blockIdx.x * blockDim.x + threadIdx.x;
    const int e0 = t * 4;
    if (e0 >= num_edges) return;

    const float w0 = W[0], w1 = W[1], w2 = W[2];
    const float bb = b[0];
    const float ms = min_sum_scaler[0];
    const float cp = cycle_penalty[0];

    // Vectorized streaming loads: 4 edges per thread (12 B/edge streaming).
    const int4   s4  = *reinterpret_cast<const int4*>(edge_src + e0);
    const int4   d4  = *reinterpret_cast<const int4*>(edge_dst + e0);
    const float4 cm4 = *reinterpret_cast<const float4*>(cycle_mask + e0);

    const int   srcs[4] = { s4.x, s4.y, s4.z, s4.w };
    const int   dsts[4] = { d4.x, d4.y, d4.z, d4.w };
    const float cms[4]  = { cm4.x, cm4.y, cm4.z, cm4.w };

    // Batch the 8 scattered gathers first: overlap L1/L2 latencies (MLP=8).
    float xs[4], xd[4];
    #pragma unroll
    for (int k = 0; k < 4; ++k) {
        xs[k] = __ldg(node_features + srcs[k]);
        xd[k] = __ldg(node_features + dsts[k]);
    }

    #pragma unroll
    for (int k = 0; k < 4; ++k) {
        const float cm = cms[k];
        float raw = fmaf(xs[k], w0, fmaf(xd[k], w1, fmaf(cm, w2, bb)));
        raw = (raw > 0.f) ? raw : 0.01f * raw;            // leaky_relu
        raw = fmaf(cm, cp, raw);
        const float att = __frcp_rn(1.f + __expf(-raw));  // sigmoid
        const float msg = xs[k] * att * ms;
        atomicAdd(out + dsts[k], msg);                    // REDG (return unused)
    }
}

extern "C" void kernel_launch(void* const* d_in, const int* in_sizes, int n_in,
                              void* d_out, int out_size) {
    const float* node_features  = (const float*)d_in[0];
    const int*   edge_index     = (const int*)d_in[1];   // [2, E] int32
    const float* cycle_mask     = (const float*)d_in[2];
    const float* W              = (const float*)d_in[3];
    const float* b              = (const float*)d_in[4];
    const float* min_sum_scaler = (const float*)d_in[5];
    const float* cycle_penalty  = (const float*)d_in[6];
    float*       out            = (float*)d_out;

    const int num_edges = in_sizes[2];          // cycle_mask length = E
    const int num_nodes = out_size;

    // 1) Zero the (poisoned) output.
    {
        int n4 = num_nodes / 4;
        int threads = 256;
        int blocks = (n4 + threads - 1) / threads;
        zero_out_kernel<<<blocks, threads>>>((float4*)out, n4);
    }

    // 2) Edge kernel: 4 edges/thread, 512-thread blocks.
    {
        int threads = 512;
        int nthreads = num_edges / 4;
        int blocks = (nthreads + threads - 1) / threads;
        cagat_edge_kernel<<<blocks, threads>>>(
            node_features,
            edge_index,                // row 0: src
            edge_index + num_edges,    // row 1: dst
            cycle_mask,
            W, b, min_sum_scaler, cycle_penalty,
            out, num_edges);
    }
}